// round 1
// baseline (speedup 1.0000x reference)
#include <cuda_runtime.h>
#include <math.h>

#define H 1024
#define W 1024
#define R 18
#define KS 37           // 2*R+1
#define NSTEP 16
#define VY 4            // outputs per thread in vertical blur
#define VX 4            // outputs per thread in horizontal blur
#define INV_N (1.0f/16.0f)

// Persistent scratch (statics: allowed; no runtime allocation)
__device__ float g_img[2][H*W];
__device__ float g_z[2][H*W];
__device__ float g_f[2][H*W];   // force: fx = -z*gx, fy = -z*gy
__device__ float g_t[2][H*W];   // after vertical blur
__device__ float g_v[2][H*W];   // after horizontal blur (vx, vy)
__device__ float g_K[KS];

// ---------------------------------------------------------------------------
__global__ void init_weights_k() {
    if (threadIdx.x == 0) {
        double w[KS], s = 0.0;
        for (int i = 0; i < KS; i++) {
            double d = (double)(i - R) / 6.0;
            w[i] = exp(-0.5 * d * d);
            s += w[i];
        }
        for (int i = 0; i < KS; i++) g_K[i] = (float)(w[i] / s);
    }
}

__global__ void copy_in_k(const float* __restrict__ image,
                          const float* __restrict__ resid) {
    int i = blockIdx.x * blockDim.x + threadIdx.x;
    g_img[0][i] = image[i];
    g_z[0][i]   = resid[i];
}

__global__ void copy_out_k(float* __restrict__ out, int buf) {
    int i = blockIdx.x * blockDim.x + threadIdx.x;
    out[i] = g_img[buf][i];
}

// ---------------------------------------------------------------------------
// force: f = (-z*gx, -z*gy), central differences with replicate edges
__global__ void force_k(int cur) {
    int x = blockIdx.x * blockDim.x + threadIdx.x;
    int y = blockIdx.y;
    const float* __restrict__ img = g_img[cur];
    const float* __restrict__ z   = g_z[cur];
    int xm = max(x - 1, 0), xp = min(x + 1, W - 1);
    int ym = max(y - 1, 0), yp = min(y + 1, H - 1);
    float gx = 0.5f * (img[y * W + xp] - img[y * W + xm]);
    float gy = 0.5f * (img[yp * W + x] - img[ym * W + x]);
    float zz = z[y * W + x];
    g_f[0][y * W + x] = -zz * gx;
    g_f[1][y * W + x] = -zz * gy;
}

// ---------------------------------------------------------------------------
// vertical blur: each thread does VY consecutive rows for both channels
__global__ void vblur_k() {
    float wk[KS];
#pragma unroll
    for (int i = 0; i < KS; i++) wk[i] = g_K[i];

    int x  = blockIdx.x * blockDim.x + threadIdx.x;
    int y0 = blockIdx.y * VY;

    float a0[VY], a1[VY];
#pragma unroll
    for (int o = 0; o < VY; o++) { a0[o] = 0.f; a1[o] = 0.f; }

#pragma unroll
    for (int j = 0; j < KS + VY - 1; j++) {       // input rows y0-R+j
        int yy = y0 - R + j;
        yy = max(0, min(H - 1, yy));
        float f0 = g_f[0][yy * W + x];
        float f1 = g_f[1][yy * W + x];
#pragma unroll
        for (int o = 0; o < VY; o++) {
            int tap = j - o;
            if (tap >= 0 && tap < KS) {
                float w = wk[tap];
                a0[o] += w * f0;
                a1[o] += w * f1;
            }
        }
    }
#pragma unroll
    for (int o = 0; o < VY; o++) {
        g_t[0][(y0 + o) * W + x] = a0[o];
        g_t[1][(y0 + o) * W + x] = a1[o];
    }
}

// ---------------------------------------------------------------------------
// horizontal blur: each thread does VX consecutive cols for both channels.
// Interior threads use aligned float4 loads; edge threads clamp scalar loads.
__global__ void hblur_k() {
    float wk[KS];
#pragma unroll
    for (int i = 0; i < KS; i++) wk[i] = g_K[i];

    int t  = threadIdx.x;          // 0..255
    int y  = blockIdx.x;           // one row per block
    int x0 = t * VX;

    const float* __restrict__ row0 = g_t[0] + y * W;
    const float* __restrict__ row1 = g_t[1] + y * W;

    float a0[VX], a1[VX];
#pragma unroll
    for (int o = 0; o < VX; o++) { a0[o] = 0.f; a1[o] = 0.f; }

    if (t >= 5 && t <= 250) {
        // inputs needed: [x0-18, x0+21]; load aligned chunks [x0-20, x0+24)
        const float4* r0 = (const float4*)(row0 + x0 - 20);
        const float4* r1 = (const float4*)(row1 + x0 - 20);
#pragma unroll
        for (int c = 0; c < 11; c++) {
            float4 q0 = r0[c];
            float4 q1 = r1[c];
            float v0[4] = {q0.x, q0.y, q0.z, q0.w};
            float v1[4] = {q1.x, q1.y, q1.z, q1.w};
#pragma unroll
            for (int e = 0; e < 4; e++) {
                int j = c * 4 + e;            // input x = x0-20+j
#pragma unroll
                for (int o = 0; o < VX; o++) {
                    int tap = j - 2 - o;       // (x0-20+j) - (x0+o-18)
                    if (tap >= 0 && tap < KS) {
                        float w = wk[tap];
                        a0[o] += w * v0[e];
                        a1[o] += w * v1[e];
                    }
                }
            }
        }
    } else {
#pragma unroll
        for (int j = 0; j < KS + VX - 1; j++) {  // input x = x0-R+j
            int xx = x0 - R + j;
            xx = max(0, min(W - 1, xx));
            float v0 = row0[xx];
            float v1 = row1[xx];
#pragma unroll
            for (int o = 0; o < VX; o++) {
                int tap = j - o;
                if (tap >= 0 && tap < KS) {
                    float w = wk[tap];
                    a0[o] += w * v0;
                    a1[o] += w * v1;
                }
            }
        }
    }
#pragma unroll
    for (int o = 0; o < VX; o++) {
        // v = smooth * (RHO/MU), RHO=MU=1
        g_v[0][y * W + x0 + o] = a0[o];
        g_v[1][y * W + x0 + o] = a1[o];
    }
}

// ---------------------------------------------------------------------------
// bilinear sample with border clamping (matches map_coordinates order=1,
// mode='nearest')
__device__ __forceinline__ float bilin(const float* __restrict__ a,
                                       float cy, float cx) {
    float fy = floorf(cy), fx = floorf(cx);
    float wy = cy - fy,    wx = cx - fx;
    int y0 = (int)fy, x0 = (int)fx;
    int y0c = min(max(y0, 0), H - 1);
    int y1c = min(max(y0 + 1, 0), H - 1);
    int x0c = min(max(x0, 0), W - 1);
    int x1c = min(max(x0 + 1, 0), W - 1);
    float a00 = a[y0c * W + x0c], a01 = a[y0c * W + x1c];
    float a10 = a[y1c * W + x0c], a11 = a[y1c * W + x1c];
    float t0 = a00 + wx * (a01 - a00);
    float t1 = a10 + wx * (a11 - a10);
    return t0 + wy * (t1 - t0);
}

// divergence + semi-Lagrangian update
__global__ void advect_k(int cur, int nxt) {
    int x = blockIdx.x * blockDim.x + threadIdx.x;
    int y = blockIdx.y;
    int i = y * W + x;

    const float* __restrict__ vx = g_v[0];
    const float* __restrict__ vy = g_v[1];
    int xm = max(x - 1, 0), xp = min(x + 1, W - 1);
    int ym = max(y - 1, 0), yp = min(y + 1, H - 1);

    float dvx_dx = 0.5f * (vx[y * W + xp] - vx[y * W + xm]);
    float dvy_dy = 0.5f * (vy[yp * W + x] - vy[ym * W + x]);
    float div    = dvx_dx + dvy_dy;

    float cy = (float)y - vy[i] * INV_N;
    float cx = (float)x - vx[i] * INV_N;

    const float* __restrict__ zc = g_z[cur];
    const float* __restrict__ ic = g_img[cur];

    float zold = zc[i];
    float znew = bilin(zc, cy, cx) - zold * div * INV_N;
    float inew = bilin(ic, cy, cx) + znew * INV_N;   // * MU / N, MU = 1

    g_z[nxt][i]   = znew;
    g_img[nxt][i] = inew;
}

// ---------------------------------------------------------------------------
extern "C" void kernel_launch(void* const* d_in, const int* in_sizes, int n_in,
                              void* d_out, int out_size) {
    const float* image = (const float*)d_in[0];
    const float* resid = (const float*)d_in[1];

    init_weights_k<<<1, 32>>>();
    copy_in_k<<<(H * W) / 256, 256>>>(image, resid);

    dim3 bsP(256, 1);
    dim3 gsP(W / 256, H);

    for (int s = 0; s < NSTEP; s++) {
        int cur = s & 1, nxt = cur ^ 1;
        force_k<<<gsP, bsP>>>(cur);
        vblur_k<<<dim3(W / 256, H / VY), 256>>>();
        hblur_k<<<H, W / VX>>>();
        advect_k<<<gsP, bsP>>>(cur, nxt);
    }

    copy_out_k<<<(H * W) / 256, 256>>>((float*)d_out, NSTEP & 1);
}

// round 2
// speedup vs baseline: 1.1549x; 1.1549x over previous
#include <cuda_runtime.h>
#include <math.h>

#define H 1024
#define W 1024
#define R 18
#define KS 37           // 2*R+1
#define NSTEP 16
#define VY 4            // output rows per thread in vertical blur
#define VX 4            // output cols per thread in horizontal blur
#define W4 (W/4)
#define INV_N (1.0f/16.0f)

// Persistent scratch (device globals: allowed; no runtime allocation)
__device__ float g_img[2][H*W];
__device__ float g_z[2][H*W];
__device__ float g_f[2][H*W];   // force: fx = -z*gx, fy = -z*gy
__device__ float g_t[2][H*W];   // after vertical blur
__device__ float g_v[2][H*W];   // velocity (vx, vy)

// ---------------------------------------------------------------------------
// Gaussian weights (sigma=6, radius 18), normalized. Precomputed in double,
// emitted as literals so ptxas uses FFMA-immediate (rt=1) with zero weight
// loads. wt(i) is only ever called with compile-time-constant i (all loops
// fully unrolled), so the switch folds to a literal.
__device__ __forceinline__ float wt(int i) {
    int d = i < R ? R - i : i - R;
    switch (d) {
        case 0:  return 0.066625152f;
        case 1:  return 0.065706198f;
        case 2:  return 0.063024692f;
        case 3:  return 0.058796492f;
        case 4:  return 0.053349252f;
        case 5:  return 0.047080544f;
        case 6:  return 0.040410194f;
        case 7:  return 0.033734705f;
        case 8:  return 0.027390419f;
        case 9:  return 0.021630020f;
        case 10: return 0.016613128f;
        case 11: return 0.012410281f;
        case 12: return 0.009016734f;
        case 13: return 0.006371659f;
        case 14: return 0.004379178f;
        case 15: return 0.002927305f;
        case 16: return 0.001903181f;
        case 17: return 0.001203452f;
        case 18: return 0.000740139f;
    }
    return 0.f;
}

__device__ __forceinline__ void fma4(float4& a, float w, const float4& v) {
    a.x += w * v.x; a.y += w * v.y; a.z += w * v.z; a.w += w * v.w;
}

// ---------------------------------------------------------------------------
__global__ void copy_in_k(const float* __restrict__ image,
                          const float* __restrict__ resid) {
    int i = blockIdx.x * blockDim.x + threadIdx.x;
    ((float4*)g_img[0])[i] = ((const float4*)image)[i];
    ((float4*)g_z[0])[i]   = ((const float4*)resid)[i];
}

__global__ void copy_out_k(float* __restrict__ out, int buf) {
    int i = blockIdx.x * blockDim.x + threadIdx.x;
    ((float4*)out)[i] = ((const float4*)g_img[buf])[i];
}

// ---------------------------------------------------------------------------
// force: f = (-z*gx, -z*gy), central differences with replicate edges.
// One thread = 4 consecutive pixels (one float4).
__global__ void force_k(int cur) {
    int c = blockIdx.x * blockDim.x + threadIdx.x;   // float4 column 0..255
    int y = blockIdx.y;
    int x0 = c * 4;
    const float* __restrict__ img = g_img[cur];
    const float* __restrict__ z   = g_z[cur];
    int ym = max(y - 1, 0), yp = min(y + 1, H - 1);

    float4 ic = ((const float4*)(img + y  * W))[c];
    float4 iu = ((const float4*)(img + ym * W))[c];
    float4 id = ((const float4*)(img + yp * W))[c];
    float4 zz = ((const float4*)(z   + y  * W))[c];
    float left  = (x0 > 0)     ? img[y * W + x0 - 1] : ic.x;
    float right = (x0 + 4 < W) ? img[y * W + x0 + 4] : ic.w;

    float4 f0, f1;
    f0.x = -zz.x * 0.5f * (ic.y  - left);
    f0.y = -zz.y * 0.5f * (ic.z  - ic.x);
    f0.z = -zz.z * 0.5f * (ic.w  - ic.y);
    f0.w = -zz.w * 0.5f * (right - ic.z);
    f1.x = -zz.x * 0.5f * (id.x - iu.x);
    f1.y = -zz.y * 0.5f * (id.y - iu.y);
    f1.z = -zz.z * 0.5f * (id.z - iu.z);
    f1.w = -zz.w * 0.5f * (id.w - iu.w);

    ((float4*)g_f[0])[y * W4 + c] = f0;
    ((float4*)g_f[1])[y * W4 + c] = f1;
}

// ---------------------------------------------------------------------------
// vertical blur: one thread = one float4 column x VY rows x 2 channels
__global__ __launch_bounds__(64, 8) void vblur_k() {
    int c  = blockIdx.x * blockDim.x + threadIdx.x;  // float4 column 0..255
    int y0 = blockIdx.y * VY;

    const float4* __restrict__ f0p = (const float4*)g_f[0];
    const float4* __restrict__ f1p = (const float4*)g_f[1];

    float4 a0[VY], a1[VY];
#pragma unroll
    for (int o = 0; o < VY; o++) {
        a0[o] = make_float4(0.f, 0.f, 0.f, 0.f);
        a1[o] = make_float4(0.f, 0.f, 0.f, 0.f);
    }

#pragma unroll
    for (int j = 0; j < KS + VY - 1; j++) {      // input rows y0-R+j
        int yy = y0 - R + j;
        yy = max(0, min(H - 1, yy));
        float4 f0 = f0p[yy * W4 + c];
        float4 f1 = f1p[yy * W4 + c];
#pragma unroll
        for (int o = 0; o < VY; o++) {
            int tap = j - o;
            if (tap >= 0 && tap < KS) {
                float w = wt(tap);
                fma4(a0[o], w, f0);
                fma4(a1[o], w, f1);
            }
        }
    }
#pragma unroll
    for (int o = 0; o < VY; o++) {
        ((float4*)g_t[0])[(y0 + o) * W4 + c] = a0[o];
        ((float4*)g_t[1])[(y0 + o) * W4 + c] = a1[o];
    }
}

// ---------------------------------------------------------------------------
// horizontal blur: one thread = VX consecutive cols x 2 channels.
// Interior threads use aligned float4 loads; edge threads scalar + clamp.
__global__ void hblur_k() {
    int t  = threadIdx.x;          // 0..255
    int y  = blockIdx.x;           // one row per block
    int x0 = t * VX;

    const float* __restrict__ row0 = g_t[0] + y * W;
    const float* __restrict__ row1 = g_t[1] + y * W;

    float a0[VX], a1[VX];
#pragma unroll
    for (int o = 0; o < VX; o++) { a0[o] = 0.f; a1[o] = 0.f; }

    if (t >= 5 && t <= 250) {
        // inputs needed: [x0-18, x0+21]; load aligned chunks [x0-20, x0+24)
        const float4* r0 = (const float4*)(row0 + x0 - 20);
        const float4* r1 = (const float4*)(row1 + x0 - 20);
#pragma unroll
        for (int cch = 0; cch < 11; cch++) {
            float4 q0 = r0[cch];
            float4 q1 = r1[cch];
            float v0[4] = {q0.x, q0.y, q0.z, q0.w};
            float v1[4] = {q1.x, q1.y, q1.z, q1.w};
#pragma unroll
            for (int e = 0; e < 4; e++) {
                int j = cch * 4 + e;          // input x = x0-20+j
#pragma unroll
                for (int o = 0; o < VX; o++) {
                    int tap = j - 2 - o;       // (x0-20+j) - (x0+o-18)
                    if (tap >= 0 && tap < KS) {
                        float w = wt(tap);
                        a0[o] += w * v0[e];
                        a1[o] += w * v1[e];
                    }
                }
            }
        }
    } else {
#pragma unroll
        for (int j = 0; j < KS + VX - 1; j++) {  // input x = x0-R+j
            int xx = x0 - R + j;
            xx = max(0, min(W - 1, xx));
            float v0 = row0[xx];
            float v1 = row1[xx];
#pragma unroll
            for (int o = 0; o < VX; o++) {
                int tap = j - o;
                if (tap >= 0 && tap < KS) {
                    float w = wt(tap);
                    a0[o] += w * v0;
                    a1[o] += w * v1;
                }
            }
        }
    }
#pragma unroll
    for (int o = 0; o < VX; o++) {
        // v = smooth * (RHO/MU), RHO=MU=1
        g_v[0][y * W + x0 + o] = a0[o];
        g_v[1][y * W + x0 + o] = a1[o];
    }
}

// ---------------------------------------------------------------------------
// bilinear sample with border clamping (matches map_coordinates order=1,
// mode='nearest')
__device__ __forceinline__ float bilin(const float* __restrict__ a,
                                       float cy, float cx) {
    float fy = floorf(cy), fx = floorf(cx);
    float wy = cy - fy,    wx = cx - fx;
    int y0 = (int)fy, x0 = (int)fx;
    int y0c = min(max(y0, 0), H - 1);
    int y1c = min(max(y0 + 1, 0), H - 1);
    int x0c = min(max(x0, 0), W - 1);
    int x1c = min(max(x0 + 1, 0), W - 1);
    float a00 = a[y0c * W + x0c], a01 = a[y0c * W + x1c];
    float a10 = a[y1c * W + x0c], a11 = a[y1c * W + x1c];
    float t0 = a00 + wx * (a01 - a00);
    float t1 = a10 + wx * (a11 - a10);
    return t0 + wy * (t1 - t0);
}

// divergence + semi-Lagrangian update; one thread = 4 consecutive pixels
__global__ void advect_k(int cur, int nxt) {
    int c = blockIdx.x * blockDim.x + threadIdx.x;   // float4 column 0..255
    int y = blockIdx.y;
    int x0 = c * 4;
    int rc = y * W4 + c;

    const float4* __restrict__ vx4 = (const float4*)g_v[0];
    const float4* __restrict__ vy4 = (const float4*)g_v[1];
    int ym = max(y - 1, 0), yp = min(y + 1, H - 1);

    float4 vxc = vx4[rc];
    float4 vyc = vy4[rc];
    float4 vyu = vy4[ym * W4 + c];
    float4 vyd = vy4[yp * W4 + c];
    float vxl = (x0 > 0)     ? g_v[0][y * W + x0 - 1] : vxc.x;
    float vxr = (x0 + 4 < W) ? g_v[0][y * W + x0 + 4] : vxc.w;

    float div[4];
    div[0] = 0.5f * (vxc.y - vxl)   + 0.5f * (vyd.x - vyu.x);
    div[1] = 0.5f * (vxc.z - vxc.x) + 0.5f * (vyd.y - vyu.y);
    div[2] = 0.5f * (vxc.w - vxc.y) + 0.5f * (vyd.z - vyu.z);
    div[3] = 0.5f * (vxr   - vxc.z) + 0.5f * (vyd.w - vyu.w);

    const float* __restrict__ zc = g_z[cur];
    const float* __restrict__ ic = g_img[cur];
    float4 zold = ((const float4*)zc)[rc];

    float vxa[4] = {vxc.x, vxc.y, vxc.z, vxc.w};
    float vya[4] = {vyc.x, vyc.y, vyc.z, vyc.w};
    float zoa[4] = {zold.x, zold.y, zold.z, zold.w};
    float zn[4], in_[4];
#pragma unroll
    for (int e = 0; e < 4; e++) {
        float cy = (float)y        - vya[e] * INV_N;
        float cx = (float)(x0 + e) - vxa[e] * INV_N;
        float zw = bilin(zc, cy, cx);
        float iw = bilin(ic, cy, cx);
        zn[e]  = zw - zoa[e] * div[e] * INV_N;
        in_[e] = iw + zn[e] * INV_N;        // * MU / N, MU = 1
    }
    ((float4*)g_z[nxt])[rc]   = make_float4(zn[0], zn[1], zn[2], zn[3]);
    ((float4*)g_img[nxt])[rc] = make_float4(in_[0], in_[1], in_[2], in_[3]);
}

// ---------------------------------------------------------------------------
extern "C" void kernel_launch(void* const* d_in, const int* in_sizes, int n_in,
                              void* d_out, int out_size) {
    const float* image = (const float*)d_in[0];
    const float* resid = (const float*)d_in[1];

    copy_in_k<<<(H * W / 4) / 256, 256>>>(image, resid);

    for (int s = 0; s < NSTEP; s++) {
        int cur = s & 1, nxt = cur ^ 1;
        force_k<<<dim3(W4 / 128, H), 128>>>(cur);
        vblur_k<<<dim3(W4 / 64, H / VY), 64>>>();
        hblur_k<<<H, W / VX>>>();
        advect_k<<<dim3(W4 / 64, H), 64>>>(cur, nxt);
    }

    copy_out_k<<<(H * W / 4) / 256, 256>>>((float*)d_out, NSTEP & 1);
}

// round 3
// speedup vs baseline: 1.2759x; 1.1048x over previous
#include <cuda_runtime.h>
#include <math.h>

#define H 1024
#define W 1024
#define R 18
#define KS 37           // 2*R+1
#define NSTEP 16
#define VY 8            // output rows per thread in vertical blur
#define VX 8            // output cols per thread in horizontal blur
#define W4 (W/4)
#define INV_N (1.0f/16.0f)

// Persistent scratch (device globals: allowed; no runtime allocation)
__device__ float g_img[2][H*W];
__device__ float g_z[2][H*W];
__device__ float g_f[2][H*W];   // force: fx = -z*gx, fy = -z*gy
__device__ float g_t[2][H*W];   // after vertical blur
__device__ float g_v[2][H*W];   // velocity (vx, vy)

// ---------------------------------------------------------------------------
// Gaussian weights (sigma=6, radius 18), normalized; literals -> FFMA-imm.
__device__ __forceinline__ float wt(int i) {
    int d = i < R ? R - i : i - R;
    switch (d) {
        case 0:  return 0.066625152f;
        case 1:  return 0.065706198f;
        case 2:  return 0.063024692f;
        case 3:  return 0.058796492f;
        case 4:  return 0.053349252f;
        case 5:  return 0.047080544f;
        case 6:  return 0.040410194f;
        case 7:  return 0.033734705f;
        case 8:  return 0.027390419f;
        case 9:  return 0.021630020f;
        case 10: return 0.016613128f;
        case 11: return 0.012410281f;
        case 12: return 0.009016734f;
        case 13: return 0.006371659f;
        case 14: return 0.004379178f;
        case 15: return 0.002927305f;
        case 16: return 0.001903181f;
        case 17: return 0.001203452f;
        case 18: return 0.000740139f;
    }
    return 0.f;
}

__device__ __forceinline__ void fma4(float4& a, float w, const float4& v) {
    a.x += w * v.x; a.y += w * v.y; a.z += w * v.z; a.w += w * v.w;
}
__device__ __forceinline__ float get4(const float4& q, int e) {
    return e == 0 ? q.x : e == 1 ? q.y : e == 2 ? q.z : q.w;
}

// ---------------------------------------------------------------------------
// force: f = (-z*gx, -z*gy), central differences with replicate edges.
// One thread = 4 consecutive pixels (one float4).
__global__ __launch_bounds__(128) void force_k(const float* __restrict__ img,
                                               const float* __restrict__ z) {
    int c = blockIdx.x * blockDim.x + threadIdx.x;   // float4 column 0..255
    int y = blockIdx.y;
    int x0 = c * 4;
    int ym = max(y - 1, 0), yp = min(y + 1, H - 1);

    float4 ic = ((const float4*)(img + y  * W))[c];
    float4 iu = ((const float4*)(img + ym * W))[c];
    float4 id = ((const float4*)(img + yp * W))[c];
    float4 zz = ((const float4*)(z   + y  * W))[c];
    float left  = (x0 > 0)     ? img[y * W + x0 - 1] : ic.x;
    float right = (x0 + 4 < W) ? img[y * W + x0 + 4] : ic.w;

    float4 f0, f1;
    f0.x = -zz.x * 0.5f * (ic.y  - left);
    f0.y = -zz.y * 0.5f * (ic.z  - ic.x);
    f0.z = -zz.z * 0.5f * (ic.w  - ic.y);
    f0.w = -zz.w * 0.5f * (right - ic.z);
    f1.x = -zz.x * 0.5f * (id.x - iu.x);
    f1.y = -zz.y * 0.5f * (id.y - iu.y);
    f1.z = -zz.z * 0.5f * (id.z - iu.z);
    f1.w = -zz.w * 0.5f * (id.w - iu.w);

    ((float4*)g_f[0])[y * W4 + c] = f0;
    ((float4*)g_f[1])[y * W4 + c] = f1;
}

// ---------------------------------------------------------------------------
// vertical blur: one thread = one float4 column x VY rows x 2 channels
__global__ __launch_bounds__(64, 4) void vblur_k() {
    int c  = blockIdx.x * blockDim.x + threadIdx.x;  // float4 column 0..255
    int y0 = blockIdx.y * VY;

    const float4* __restrict__ f0p = (const float4*)g_f[0];
    const float4* __restrict__ f1p = (const float4*)g_f[1];

    float4 a0[VY], a1[VY];
#pragma unroll
    for (int o = 0; o < VY; o++) {
        a0[o] = make_float4(0.f, 0.f, 0.f, 0.f);
        a1[o] = make_float4(0.f, 0.f, 0.f, 0.f);
    }

#pragma unroll
    for (int j = 0; j < KS + VY - 1; j++) {      // input rows y0-R+j
        int yy = y0 - R + j;
        yy = max(0, min(H - 1, yy));
        float4 f0 = f0p[yy * W4 + c];
        float4 f1 = f1p[yy * W4 + c];
#pragma unroll
        for (int o = 0; o < VY; o++) {
            int tap = j - o;
            if (tap >= 0 && tap < KS) {
                float w = wt(tap);
                fma4(a0[o], w, f0);
                fma4(a1[o], w, f1);
            }
        }
    }
#pragma unroll
    for (int o = 0; o < VY; o++) {
        ((float4*)g_t[0])[(y0 + o) * W4 + c] = a0[o];
        ((float4*)g_t[1])[(y0 + o) * W4 + c] = a1[o];
    }
}

// ---------------------------------------------------------------------------
// horizontal blur: one thread = VX=8 consecutive cols, channels sequential.
// Interior threads: 12 aligned float4 loads per channel. Edge: scalar+clamp.
__global__ __launch_bounds__(128, 4) void hblur_k() {
    int t  = threadIdx.x;          // 0..127
    int y  = blockIdx.x;           // one row per block
    int x0 = t * VX;

    bool interior = (t >= 3 && t <= 124);

#pragma unroll
    for (int ch = 0; ch < 2; ch++) {
        const float* __restrict__ row = g_t[ch] + y * W;
        float a[VX];
#pragma unroll
        for (int o = 0; o < VX; o++) a[o] = 0.f;

        if (interior) {
            // inputs needed: [x0-18, x0+25]; aligned window [x0-20, x0+28)
            const float4* r = (const float4*)(row + x0 - 20);
#pragma unroll
            for (int c4 = 0; c4 < 12; c4++) {
                float4 q = r[c4];
#pragma unroll
                for (int e = 0; e < 4; e++) {
                    int j = c4 * 4 + e;            // input x = x0-20+j
                    float v = get4(q, e);
#pragma unroll
                    for (int o = 0; o < VX; o++) {
                        int tap = j - 2 - o;        // (x0-20+j) - (x0+o-18)
                        if (tap >= 0 && tap < KS) a[o] += wt(tap) * v;
                    }
                }
            }
        } else {
#pragma unroll
            for (int j = 0; j < KS + VX - 1; j++) { // input x = x0-R+j
                int xx = x0 - R + j;
                xx = max(0, min(W - 1, xx));
                float v = row[xx];
#pragma unroll
                for (int o = 0; o < VX; o++) {
                    int tap = j - o;
                    if (tap >= 0 && tap < KS) a[o] += wt(tap) * v;
                }
            }
        }
        // v = smooth * (RHO/MU), RHO=MU=1
        float4* dst = (float4*)(g_v[ch] + y * W + x0);
        dst[0] = make_float4(a[0], a[1], a[2], a[3]);
        dst[1] = make_float4(a[4], a[5], a[6], a[7]);
    }
}

// ---------------------------------------------------------------------------
// bilinear sample with border clamping (map_coordinates order=1 mode='nearest')
__device__ __forceinline__ float bilin(const float* __restrict__ a,
                                       float cy, float cx) {
    float fy = floorf(cy), fx = floorf(cx);
    float wy = cy - fy,    wx = cx - fx;
    int y0 = (int)fy, x0 = (int)fx;
    int y0c = min(max(y0, 0), H - 1);
    int y1c = min(max(y0 + 1, 0), H - 1);
    int x0c = min(max(x0, 0), W - 1);
    int x1c = min(max(x0 + 1, 0), W - 1);
    float a00 = a[y0c * W + x0c], a01 = a[y0c * W + x1c];
    float a10 = a[y1c * W + x0c], a11 = a[y1c * W + x1c];
    float t0 = a00 + wx * (a01 - a00);
    float t1 = a10 + wx * (a11 - a10);
    return t0 + wy * (t1 - t0);
}

// divergence + semi-Lagrangian update; one thread = 4 consecutive pixels
__global__ __launch_bounds__(128) void advect_k(const float* __restrict__ zc,
                                                const float* __restrict__ ic,
                                                float* __restrict__ zout,
                                                float* __restrict__ iout) {
    int c = blockIdx.x * blockDim.x + threadIdx.x;   // float4 column 0..255
    int y = blockIdx.y;
    int x0 = c * 4;
    int rc = y * W4 + c;

    const float4* __restrict__ vx4 = (const float4*)g_v[0];
    const float4* __restrict__ vy4 = (const float4*)g_v[1];
    int ym = max(y - 1, 0), yp = min(y + 1, H - 1);

    float4 vxc = vx4[rc];
    float4 vyc = vy4[rc];
    float4 vyu = vy4[ym * W4 + c];
    float4 vyd = vy4[yp * W4 + c];
    float vxl = (x0 > 0)     ? g_v[0][y * W + x0 - 1] : vxc.x;
    float vxr = (x0 + 4 < W) ? g_v[0][y * W + x0 + 4] : vxc.w;

    float div[4];
    div[0] = 0.5f * (vxc.y - vxl)   + 0.5f * (vyd.x - vyu.x);
    div[1] = 0.5f * (vxc.z - vxc.x) + 0.5f * (vyd.y - vyu.y);
    div[2] = 0.5f * (vxc.w - vxc.y) + 0.5f * (vyd.z - vyu.z);
    div[3] = 0.5f * (vxr   - vxc.z) + 0.5f * (vyd.w - vyu.w);

    float4 zold = ((const float4*)zc)[rc];

    float vxa[4] = {vxc.x, vxc.y, vxc.z, vxc.w};
    float vya[4] = {vyc.x, vyc.y, vyc.z, vyc.w};
    float zoa[4] = {zold.x, zold.y, zold.z, zold.w};
    float zn[4], in_[4];
#pragma unroll
    for (int e = 0; e < 4; e++) {
        float cy = (float)y        - vya[e] * INV_N;
        float cx = (float)(x0 + e) - vxa[e] * INV_N;
        float zw = bilin(zc, cy, cx);
        float iw = bilin(ic, cy, cx);
        zn[e]  = zw - zoa[e] * div[e] * INV_N;
        in_[e] = iw + zn[e] * INV_N;        // * MU / N, MU = 1
    }
    ((float4*)zout)[rc] = make_float4(zn[0], zn[1], zn[2], zn[3]);
    ((float4*)iout)[rc] = make_float4(in_[0], in_[1], in_[2], in_[3]);
}

// ---------------------------------------------------------------------------
extern "C" void kernel_launch(void* const* d_in, const int* in_sizes, int n_in,
                              void* d_out, int out_size) {
    const float* image = (const float*)d_in[0];
    const float* resid = (const float*)d_in[1];

    void* p_img = nullptr; void* p_z = nullptr;
    cudaGetSymbolAddress(&p_img, g_img);
    cudaGetSymbolAddress(&p_z, g_z);
    float* imgbuf[2] = {(float*)p_img, (float*)p_img + H * W};
    float* zbuf[2]   = {(float*)p_z,   (float*)p_z   + H * W};

    dim3 gsP(W4 / 128, H);

    for (int s = 0; s < NSTEP; s++) {
        const float* ic = (s == 0) ? image : imgbuf[s & 1];
        const float* zc = (s == 0) ? resid : zbuf[s & 1];
        float* iout = (s == NSTEP - 1) ? (float*)d_out : imgbuf[(s + 1) & 1];
        float* zout = zbuf[(s + 1) & 1];

        force_k<<<gsP, 128>>>(ic, zc);
        vblur_k<<<dim3(W4 / 64, H / VY), 64>>>();
        hblur_k<<<H, W / VX>>>();
        advect_k<<<gsP, 128>>>(zc, ic, zout, iout);
    }
}